// round 12
// baseline (speedup 1.0000x reference)
#include <cuda_runtime.h>
#include <math.h>

typedef unsigned long long u64;
typedef unsigned int u32;

// Problem dims
#define B_  256
#define S_  2048
#define I_  32
#define H_  18

// Scan pipeline config: 2 temporal segments, quad-chain warps, CH=16.
#define CH      16               // timesteps per chunk
#define HALF    (S_ / 2)         // 1024 steps per segment
#define NC0     (HALF / CH)      // 64 chunks (segment 0)
#define BURN    128              // burn-in steps for segment 1
#define BURNC   (BURN / CH)      // 8 burn-in chunks
#define NC1     (NC0 + BURNC)    // 72 chunks (segment 1)
#define RS2     10               // ring row stride in u64 (80 bytes)
#define ROWB    80

// Scratch: layer-2 hidden sequence [B, S, H] f32 (36 MB).
__device__ float g_h2[(size_t)B_ * S_ * H_];

// ---------------- packed f32x2 helpers ----------------
__device__ __forceinline__ void fma2(u64& d, u64 a, u64 b) {
    asm("fma.rn.f32x2 %0, %1, %2, %0;" : "+l"(d) : "l"(a), "l"(b));
}
__device__ __forceinline__ u64 add2(u64 a, u64 b) {
    u64 d; asm("add.rn.f32x2 %0, %1, %2;" : "=l"(d) : "l"(a), "l"(b)); return d;
}
__device__ __forceinline__ float hsum2(u64 a) {
    float x, y; asm("mov.b64 {%0, %1}, %2;" : "=f"(x), "=f"(y) : "l"(a));
    return x + y;
}
__device__ __forceinline__ u64 pack2(float x, float y) {
    u64 d; asm("mov.b64 %0, {%1, %2};" : "=l"(d) : "f"(x), "f"(y)); return d;
}
__device__ __forceinline__ float tanh_fast(float x) {
    float r; asm("tanh.approx.f32 %0, %1;" : "=f"(r) : "f"(x)); return r;
}
// Ordered shared ops (same-warp in-order smem pipe; volatile pins order).
__device__ __forceinline__ void sts_f32(u32 addr, float v) {
    asm volatile("st.shared.f32 [%0], %1;" :: "r"(addr), "f"(v));
}
__device__ __forceinline__ u64 lds_u64(u32 addr) {
    u64 v; asm volatile("ld.shared.b64 %0, [%1];" : "=l"(v) : "r"(addr)); return v;
}
__device__ __forceinline__ void lds_pair(u32 addr, u64& x, u64& y) {
    asm volatile("ld.shared.v2.b64 {%0,%1}, [%2];" : "=l"(x), "=l"(y) : "r"(addr));
}
__device__ __forceinline__ float lds_f32(u32 addr) {
    float v; asm volatile("ld.shared.f32 %0, [%1];" : "=f"(v) : "r"(addr)); return v;
}

struct Acc { u64 a0, a1, a2; };

// 18-value dot from a ring row at smem addr `hp` (16B-aligned): 4x LDS.128 + 1x LDS.64.
__device__ __forceinline__ void rowdot(Acc& A, const u64* w, u32 hp) {
    u64 v0, v1, v2, v3, v4, v5, v6, v7, v8;
    lds_pair(hp,      v0, v1);
    lds_pair(hp + 16, v2, v3);
    lds_pair(hp + 32, v4, v5);
    lds_pair(hp + 48, v6, v7);
    v8 = lds_u64(hp + 64);
    fma2(A.a0, w[0], v0); fma2(A.a1, w[1], v1); fma2(A.a2, w[2], v2);
    fma2(A.a0, w[3], v3); fma2(A.a1, w[4], v4); fma2(A.a2, w[5], v5);
    fma2(A.a0, w[6], v6); fma2(A.a1, w[7], v7); fma2(A.a2, w[8], v8);
}
__device__ __forceinline__ float finish(Acc& A) {
    return tanh_fast(hsum2(add2(add2(A.a0, A.a1), A.a2)));
}

// ---------------------------------------------------------------------------
// Kernel A: fused 3-layer RNN scan, 2-way temporal segmentation,
// QUAD-CHAIN warps: 4 warps per block (one per role), each warp runs all
// 4 chains (2 batches x 2 segments). Grid 128 = one wave, 1 warp/SMSP.
// Cross-chain ILP hides the smem round-trip; low warp count keeps the
// MIO queueing delay on the serial chain minimal (R7 measurement: 130cyc).
// ---------------------------------------------------------------------------
__global__ __launch_bounds__(128, 1)
void rnn_scan_kernel(const float* __restrict__ input,
                     const float* __restrict__ hidden,
                     const float* __restrict__ Wih0, const float* __restrict__ bih0,
                     const float* __restrict__ Whh0, const float* __restrict__ bhh0,
                     const float* __restrict__ Wih1, const float* __restrict__ bih1,
                     const float* __restrict__ Whh1, const float* __restrict__ bhh1,
                     const float* __restrict__ Wih2, const float* __restrict__ bih2,
                     const float* __restrict__ Whh2, const float* __restrict__ bhh2,
                     float* __restrict__ out, int write_hidden)
{
    __shared__ __align__(16) float4 s_x [4][CH][8];       // x staging (role0)
    __shared__ __align__(16) u64    s_xw[4][2][CH][RS2];  // role0 -> role1
    __shared__ __align__(16) u64    s_h0[4][2][CH][RS2];  // role1 -> role2 (+ self)
    __shared__ __align__(16) u64    s_h1[4][2][CH][RS2];  // role2 -> role3 (+ self)
    __shared__ __align__(16) u64    s_h2[4][2][CH][RS2];  // role3 self

    const int tid  = threadIdx.x;
    const int role = tid >> 5;                  // warp id = role, 1 per SMSP
    const int lane = tid & 31;
    const int jj   = (lane < H_) ? lane : 0;    // clamped; dup lanes benign
    const bool act = (lane < H_);

    // Chains k=0..3: bi = k&1, seg = k>>1.
    const int bA = blockIdx.x * 2;              // batch of chains 0,2
    // batch of chain k: bA + (k&1)

    u64 wA[16];      // role0 input weight pairs
    u64 wP[9];       // roles 2/3 input-transform weight pairs
    u64 wR[9];       // roles 1-3 recurrent weight pairs
    float bsum = 0.f;
    float h[4] = {0.f, 0.f, 0.f, 0.f};

    if (role == 0) {
        const u64* w = (const u64*)(Wih0 + jj * I_);
        #pragma unroll
        for (int m = 0; m < 16; ++m) wA[m] = __ldg(&w[m]);
        bsum = __ldg(&bih0[jj]) + __ldg(&bhh0[jj]);
    } else if (role == 1) {
        const u64* w = (const u64*)(Whh0 + jj * H_);
        #pragma unroll
        for (int m = 0; m < 9; ++m) wR[m] = __ldg(&w[m]);
        h[0] = __ldg(&hidden[0 * B_ * H_ + (bA + 0) * H_ + jj]);
        h[1] = __ldg(&hidden[0 * B_ * H_ + (bA + 1) * H_ + jj]);
        #pragma unroll
        for (int k = 0; k < 4; ++k)
            ((float*)&s_h0[k][1][CH - 1][0])[jj] = h[k];
    } else if (role == 2) {
        const u64* wp = (const u64*)(Wih1 + jj * H_);
        const u64* wr = (const u64*)(Whh1 + jj * H_);
        #pragma unroll
        for (int m = 0; m < 9; ++m) { wP[m] = __ldg(&wp[m]); wR[m] = __ldg(&wr[m]); }
        bsum = __ldg(&bih1[jj]) + __ldg(&bhh1[jj]);
        h[0] = __ldg(&hidden[1 * B_ * H_ + (bA + 0) * H_ + jj]);
        h[1] = __ldg(&hidden[1 * B_ * H_ + (bA + 1) * H_ + jj]);
        #pragma unroll
        for (int k = 0; k < 4; ++k)
            ((float*)&s_h1[k][1][CH - 1][0])[jj] = h[k];
    } else {
        const u64* wp = (const u64*)(Wih2 + jj * H_);
        const u64* wr = (const u64*)(Whh2 + jj * H_);
        #pragma unroll
        for (int m = 0; m < 9; ++m) { wP[m] = __ldg(&wp[m]); wR[m] = __ldg(&wr[m]); }
        bsum = __ldg(&bih2[jj]) + __ldg(&bhh2[jj]);
        h[0] = __ldg(&hidden[2 * B_ * H_ + (bA + 0) * H_ + jj]);
        h[1] = __ldg(&hidden[2 * B_ * H_ + (bA + 1) * H_ + jj]);
        #pragma unroll
        for (int k = 0; k < 4; ++k)
            ((float*)&s_h2[k][1][CH - 1][0])[jj] = h[k];
    }
    const u64 binit = pack2(bsum, 0.f);

    // smem bases per chain
    u32 self_b[4] = {0, 0, 0, 0}, pv_b[4] = {0, 0, 0, 0};
    u32 xw_b[4], x_b[4];
    #pragma unroll
    for (int k = 0; k < 4; ++k) {
        xw_b[k] = (u32)__cvta_generic_to_shared(&s_xw[k][0][0][0]);
        x_b[k]  = (u32)__cvta_generic_to_shared(&s_x[k][0][0]);
        if (role == 1) {
            self_b[k] = (u32)__cvta_generic_to_shared(&s_h0[k][0][0][0]);
        } else if (role == 2) {
            self_b[k] = (u32)__cvta_generic_to_shared(&s_h1[k][0][0][0]);
            pv_b[k]   = (u32)__cvta_generic_to_shared(&s_h0[k][0][0][0]);
        } else if (role == 3) {
            self_b[k] = (u32)__cvta_generic_to_shared(&s_h2[k][0][0][0]);
            pv_b[k]   = (u32)__cvta_generic_to_shared(&s_h1[k][0][0][0]);
        }
    }

    for (int ss = 0; ss < NC1 + 3; ++ss) {
        const int c = ss - role;
        if ((unsigned)c < (unsigned)NC1) {
            const int slot = c & 1;
            // Chain k active? seg0 chains (k<2) have NC0 chunks, seg1 NC1.
            bool on[4];
            int  t0c[4];
            #pragma unroll
            for (int k = 0; k < 4; ++k) {
                const int sg = k >> 1;
                on[k]  = c < (sg ? NC1 : NC0);
                t0c[k] = (sg ? (HALF - BURN) : 0) + c * CH;
            }
            if (role == 0) {
                // Stage x chunks for active chains (coalesced float4).
                #pragma unroll
                for (int k = 0; k < 4; ++k) {
                    if (!on[k]) continue;
                    const int b = bA + (k & 1);
                    const float4* xg =
                        (const float4*)(input + ((size_t)b * S_ + t0c[k]) * I_);
                    float4* xs = (float4*)&s_x[k][0][0];
                    #pragma unroll
                    for (int i = 0; i < 4; ++i)
                        xs[lane + 32 * i] = __ldg(&xg[lane + 32 * i]);
                }
                __syncwarp();
                u32 xa[4], xw[4];
                #pragma unroll
                for (int k = 0; k < 4; ++k) {
                    xa[k] = x_b[k];
                    xw[k] = xw_b[k] + slot * CH * ROWB + 4 * jj;
                }
                #pragma unroll 2
                for (int t = 0; t < CH; ++t) {
                    #pragma unroll
                    for (int k = 0; k < 4; ++k) {
                        if (!on[k]) continue;
                        u64 x0, x1, x2, x3, x4, x5, x6, x7;
                        u64 x8, x9, xA, xB, xC, xD, xE, xF;
                        lds_pair(xa[k],       x0, x1);  lds_pair(xa[k] + 16,  x2, x3);
                        lds_pair(xa[k] + 32,  x4, x5);  lds_pair(xa[k] + 48,  x6, x7);
                        lds_pair(xa[k] + 64,  x8, x9);  lds_pair(xa[k] + 80,  xA, xB);
                        lds_pair(xa[k] + 96,  xC, xD);  lds_pair(xa[k] + 112, xE, xF);
                        u64 a0 = binit, a1 = 0ull, a2 = 0ull, a3 = 0ull;
                        fma2(a0, wA[0],  x0); fma2(a1, wA[1],  x1);
                        fma2(a2, wA[2],  x2); fma2(a3, wA[3],  x3);
                        fma2(a0, wA[4],  x4); fma2(a1, wA[5],  x5);
                        fma2(a2, wA[6],  x6); fma2(a3, wA[7],  x7);
                        fma2(a0, wA[8],  x8); fma2(a1, wA[9],  x9);
                        fma2(a2, wA[10], xA); fma2(a3, wA[11], xB);
                        fma2(a0, wA[12], xC); fma2(a1, wA[13], xD);
                        fma2(a2, wA[14], xE); fma2(a3, wA[15], xF);
                        a0 = add2(a0, a1); a2 = add2(a2, a3); a0 = add2(a0, a2);
                        sts_f32(xw[k], hsum2(a0));
                        xa[k] += 128; xw[k] += ROWB;
                    }
                }
            } else if (role == 1) {
                u32 hp[4], cur[4], xw[4];
                #pragma unroll
                for (int k = 0; k < 4; ++k) {
                    hp[k]  = self_b[k] + ((slot ^ 1) * CH + CH - 1) * ROWB;
                    cur[k] = self_b[k] + slot * CH * ROWB;
                    xw[k]  = xw_b[k] + slot * CH * ROWB + 4 * jj;
                }
                #pragma unroll 2
                for (int t = 0; t < CH; ++t) {
                    Acc A[4];
                    #pragma unroll
                    for (int k = 0; k < 4; ++k) {
                        if (!on[k]) continue;
                        A[k].a0 = pack2(lds_f32(xw[k]), 0.f);
                        A[k].a1 = 0ull; A[k].a2 = 0ull;
                        rowdot(A[k], wR, hp[k]);
                    }
                    #pragma unroll
                    for (int k = 0; k < 4; ++k) {
                        if (!on[k]) continue;
                        h[k] = finish(A[k]);
                        sts_f32(cur[k] + 4 * jj, h[k]);
                        hp[k] = cur[k]; cur[k] += ROWB; xw[k] += ROWB;
                    }
                }
            } else {
                u32 hp[4], cur[4], pva[4];
                float* go[4];
                bool wr[4];
                #pragma unroll
                for (int k = 0; k < 4; ++k) {
                    hp[k]  = self_b[k] + ((slot ^ 1) * CH + CH - 1) * ROWB;
                    cur[k] = self_b[k] + slot * CH * ROWB;
                    pva[k] = pv_b[k] + slot * CH * ROWB;
                    const int b = bA + (k & 1);
                    go[k] = g_h2 + ((size_t)b * S_ + t0c[k]) * H_;
                    wr[k] = (role == 3) && on[k] &&
                            (((k >> 1) == 0) || (c >= BURNC));
                }
                #pragma unroll 2
                for (int t = 0; t < CH; ++t) {
                    Acc A[4];
                    #pragma unroll
                    for (int k = 0; k < 4; ++k) {
                        if (!on[k]) continue;
                        A[k].a0 = binit; A[k].a1 = 0ull; A[k].a2 = 0ull;
                        rowdot(A[k], wP, pva[k]);   // producer row (barrier-sep)
                        rowdot(A[k], wR, hp[k]);    // self row (same-warp ordered)
                    }
                    #pragma unroll
                    for (int k = 0; k < 4; ++k) {
                        if (!on[k]) continue;
                        h[k] = finish(A[k]);
                        sts_f32(cur[k] + 4 * jj, h[k]);
                        if (wr[k]) go[k][t * H_ + jj] = h[k];
                        hp[k] = cur[k]; cur[k] += ROWB; pva[k] += ROWB;
                    }
                }
            }
        }
        __syncthreads();
    }

    // Final hidden states come from the segment-1 chains (k=2,3).
    if (write_hidden && role >= 1 && act) {
        out[(size_t)B_ * S_ + (size_t)(role - 1) * B_ * H_ + (bA + 0) * H_ + lane] = h[2];
        out[(size_t)B_ * S_ + (size_t)(role - 1) * B_ * H_ + (bA + 1) * H_ + lane] = h[3];
    }
}

// ---------------------------------------------------------------------------
// Kernel B: MLP head (unchanged from best).
// ---------------------------------------------------------------------------
__global__ __launch_bounds__(256, 5)
void mlp_head_kernel(const float* __restrict__ W1, const float* __restrict__ b1,
                     const float* __restrict__ W2, const float* __restrict__ b2,
                     const float* __restrict__ W3, const float* __restrict__ b3,
                     const float* __restrict__ W4, const float* __restrict__ b4,
                     const float* __restrict__ W5, const float* __restrict__ b5,
                     const float* __restrict__ W6, const float* __restrict__ b6,
                     float* __restrict__ out)
{
    __shared__ u64 sROW[256 * 9];
    __shared__ u64 sW1[162], sW2[90], sW3[40], sW4[16], sW5[4];
    __shared__ float sb1[18], sb2[10], sb3[8], sb4[4], sb5[2], sW6f[2], sb6f[1];

    const int tid = threadIdx.x;
    if (tid < 162) sW1[tid] = __ldg((const u64*)W1 + tid);
    if (tid < 90)  sW2[tid] = __ldg((const u64*)W2 + tid);
    if (tid < 40)  sW3[tid] = __ldg((const u64*)W3 + tid);
    if (tid < 16)  sW4[tid] = __ldg((const u64*)W4 + tid);
    if (tid < 4)  { sW5[tid] = __ldg((const u64*)W5 + tid); sb4[tid] = b4[tid]; }
    if (tid < 18)  sb1[tid] = b1[tid];
    if (tid < 10)  sb2[tid] = b2[tid];
    if (tid < 8)   sb3[tid] = b3[tid];
    if (tid < 2)  { sb5[tid] = b5[tid]; sW6f[tid] = W6[tid]; }
    if (tid == 0)  sb6f[0] = b6[0];

    const size_t base = (size_t)blockIdx.x * 256;
    const u64* gh = (const u64*)g_h2 + base * 9;
    #pragma unroll
    for (int i = 0; i < 9; ++i) sROW[tid + i * 256] = __ldg(&gh[tid + i * 256]);
    __syncthreads();

    u64 a0[9];
    #pragma unroll
    for (int m = 0; m < 9; ++m) a0[m] = sROW[tid * 9 + m];

    float a1[18];
    #pragma unroll
    for (int j = 0; j < 18; ++j) {
        u64 acc = pack2(sb1[j], 0.f), accb = 0ull;
        #pragma unroll
        for (int m = 0; m < 9; ++m) fma2((m & 1) ? accb : acc, sW1[j * 9 + m], a0[m]);
        a1[j] = fmaxf(hsum2(add2(acc, accb)), 0.f);
    }
    u64 a1p[9];
    #pragma unroll
    for (int m = 0; m < 9; ++m) a1p[m] = pack2(a1[2 * m], a1[2 * m + 1]);

    float a2[10];
    #pragma unroll
    for (int j = 0; j < 10; ++j) {
        u64 acc = pack2(sb2[j], 0.f), accb = 0ull;
        #pragma unroll
        for (int m = 0; m < 9; ++m) fma2((m & 1) ? accb : acc, sW2[j * 9 + m], a1p[m]);
        a2[j] = fmaxf(hsum2(add2(acc, accb)), 0.f);
    }
    u64 a2p[5];
    #pragma unroll
    for (int m = 0; m < 5; ++m) a2p[m] = pack2(a2[2 * m], a2[2 * m + 1]);

    float a3[8];
    #pragma unroll
    for (int j = 0; j < 8; ++j) {
        u64 acc = pack2(sb3[j], 0.f), accb = 0ull;
        #pragma unroll
        for (int m = 0; m < 5; ++m) fma2((m & 1) ? accb : acc, sW3[j * 5 + m], a2p[m]);
        a3[j] = fmaxf(hsum2(add2(acc, accb)), 0.f);
    }
    u64 a3p[4];
    #pragma unroll
    for (int m = 0; m < 4; ++m) a3p[m] = pack2(a3[2 * m], a3[2 * m + 1]);

    float a4[4];
    #pragma unroll
    for (int j = 0; j < 4; ++j) {
        u64 acc = pack2(sb4[j], 0.f), accb = 0ull;
        #pragma unroll
        for (int m = 0; m < 4; ++m) fma2((m & 1) ? accb : acc, sW4[j * 4 + m], a3p[m]);
        a4[j] = fmaxf(hsum2(add2(acc, accb)), 0.f);
    }
    u64 a4p[2] = { pack2(a4[0], a4[1]), pack2(a4[2], a4[3]) };

    float a5[2];
    #pragma unroll
    for (int j = 0; j < 2; ++j) {
        u64 acc = pack2(sb5[j], 0.f);
        fma2(acc, sW5[j * 2 + 0], a4p[0]);
        fma2(acc, sW5[j * 2 + 1], a4p[1]);
        a5[j] = fmaxf(hsum2(acc), 0.f);
    }
    out[base + tid] = fmaf(a5[0], sW6f[0], fmaf(a5[1], sW6f[1], sb6f[0]));
}

// ---------------------------------------------------------------------------
// Launch
// ---------------------------------------------------------------------------
extern "C" void kernel_launch(void* const* d_in, const int* in_sizes, int n_in,
                              void* d_out, int out_size)
{
    const float* input  = (const float*)d_in[0];
    const float* hidden = (const float*)d_in[1];
    const float* Wih0 = (const float*)d_in[2];
    const float* bih0 = (const float*)d_in[3];
    const float* Whh0 = (const float*)d_in[4];
    const float* bhh0 = (const float*)d_in[5];
    const float* Wih1 = (const float*)d_in[6];
    const float* bih1 = (const float*)d_in[7];
    const float* Whh1 = (const float*)d_in[8];
    const float* bhh1 = (const float*)d_in[9];
    const float* Wih2 = (const float*)d_in[10];
    const float* bih2 = (const float*)d_in[11];
    const float* Whh2 = (const float*)d_in[12];
    const float* bhh2 = (const float*)d_in[13];
    const float* W1 = (const float*)d_in[14];
    const float* b1 = (const float*)d_in[15];
    const float* W2 = (const float*)d_in[16];
    const float* b2 = (const float*)d_in[17];
    const float* W3 = (const float*)d_in[18];
    const float* b3 = (const float*)d_in[19];
    const float* W4 = (const float*)d_in[20];
    const float* b4 = (const float*)d_in[21];
    const float* W5 = (const float*)d_in[22];
    const float* b5 = (const float*)d_in[23];
    const float* W6 = (const float*)d_in[24];
    const float* b6 = (const float*)d_in[25];

    float* out = (float*)d_out;
    const int write_hidden = (out_size >= B_ * S_ + 3 * B_ * H_) ? 1 : 0;

    rnn_scan_kernel<<<B_ / 2, 128>>>(input, hidden,
                                     Wih0, bih0, Whh0, bhh0,
                                     Wih1, bih1, Whh1, bhh1,
                                     Wih2, bih2, Whh2, bhh2,
                                     out, write_hidden);

    mlp_head_kernel<<<(B_ * S_) / 256, 256>>>(W1, b1, W2, b2, W3, b3,
                                              W4, b4, W5, b5, W6, b6, out);
}

// round 13
// speedup vs baseline: 1.7908x; 1.7908x over previous
#include <cuda_runtime.h>
#include <math.h>

typedef unsigned long long u64;
typedef unsigned int u32;

// Problem dims
#define B_  256
#define S_  2048
#define I_  32
#define H_  18

// Scan pipeline config: 2 temporal segments, 3 merged roles, CH=16.
#define CH      16               // timesteps per chunk
#define HALF    (S_ / 2)         // 1024 steps per segment
#define NC0     (HALF / CH)      // 64 chunks (segment 0)
#define BURN    128              // burn-in steps for segment 1
#define BURNC   (BURN / CH)      // 8 burn-in chunks
#define NC1     (NC0 + BURNC)    // 72 chunks (segment 1)
#define RS2     10               // ring row stride in u64 (80 bytes)
#define ROWB    80
#define XCHB    (CH * 128)       // bytes per x chunk buffer (16 rows x 128B)

// Scratch: layer-2 hidden sequence [B, S, H] f32 (36 MB).
__device__ float g_h2[(size_t)B_ * S_ * H_];

// ---------------- packed f32x2 helpers ----------------
__device__ __forceinline__ void fma2(u64& d, u64 a, u64 b) {
    asm("fma.rn.f32x2 %0, %1, %2, %0;" : "+l"(d) : "l"(a), "l"(b));
}
__device__ __forceinline__ u64 add2(u64 a, u64 b) {
    u64 d; asm("add.rn.f32x2 %0, %1, %2;" : "=l"(d) : "l"(a), "l"(b)); return d;
}
__device__ __forceinline__ float hsum2(u64 a) {
    float x, y; asm("mov.b64 {%0, %1}, %2;" : "=f"(x), "=f"(y) : "l"(a));
    return x + y;
}
__device__ __forceinline__ u64 pack2(float x, float y) {
    u64 d; asm("mov.b64 %0, {%1, %2};" : "=l"(d) : "f"(x), "f"(y)); return d;
}
__device__ __forceinline__ float tanh_fast(float x) {
    float r; asm("tanh.approx.f32 %0, %1;" : "=f"(r) : "f"(x)); return r;
}
// Ordered shared ops (same-warp in-order smem pipe; volatile pins order).
__device__ __forceinline__ void sts_f32(u32 addr, float v) {
    asm volatile("st.shared.f32 [%0], %1;" :: "r"(addr), "f"(v));
}
__device__ __forceinline__ void sts_f128(u32 addr, float4 v) {
    asm volatile("st.shared.v4.f32 [%0], {%1,%2,%3,%4};"
                 :: "r"(addr), "f"(v.x), "f"(v.y), "f"(v.z), "f"(v.w));
}
__device__ __forceinline__ u64 lds_u64(u32 addr) {
    u64 v; asm volatile("ld.shared.b64 %0, [%1];" : "=l"(v) : "r"(addr)); return v;
}
__device__ __forceinline__ void lds_pair(u32 addr, u64& x, u64& y) {
    asm volatile("ld.shared.v2.b64 {%0,%1}, [%2];" : "=l"(x), "=l"(y) : "r"(addr));
}

struct Acc { u64 a0, a1, a2; };

// 18-value dot from a ring row at smem addr `hp` (16B-aligned).
__device__ __forceinline__ void rowdot(Acc& A, const u64* w, u32 hp) {
    u64 v0, v1, v2, v3, v4, v5, v6, v7, v8;
    lds_pair(hp,      v0, v1);
    lds_pair(hp + 16, v2, v3);
    lds_pair(hp + 32, v4, v5);
    lds_pair(hp + 48, v6, v7);
    v8 = lds_u64(hp + 64);
    fma2(A.a0, w[0], v0); fma2(A.a1, w[1], v1); fma2(A.a2, w[2], v2);
    fma2(A.a0, w[3], v3); fma2(A.a1, w[4], v4); fma2(A.a2, w[5], v5);
    fma2(A.a0, w[6], v6); fma2(A.a1, w[7], v7); fma2(A.a2, w[8], v8);
}
__device__ __forceinline__ float finish(Acc& A) {
    return tanh_fast(hsum2(add2(add2(A.a0, A.a1), A.a2)));
}

// ---------------------------------------------------------------------------
// Kernel A: fused 3-layer RNN scan, 2-way temporal segmentation.
// 3 roles (= layers; x-transform merged into layer-0's warp) x 4 chains
// (2 batches x 2 segments) = 12 warps (384 thr). Grid 128 = one wave.
// wid = role*4 + k  ->  chain k's 3 role-warps all on SMSP k.
// Per-chain named barriers (bar.sync k+1, 96) decouple the 4 chains.
// ---------------------------------------------------------------------------
__global__ __launch_bounds__(384, 1)
void rnn_scan_kernel(const float* __restrict__ input,
                     const float* __restrict__ hidden,
                     const float* __restrict__ Wih0, const float* __restrict__ bih0,
                     const float* __restrict__ Whh0, const float* __restrict__ bhh0,
                     const float* __restrict__ Wih1, const float* __restrict__ bih1,
                     const float* __restrict__ Whh1, const float* __restrict__ bhh1,
                     const float* __restrict__ Wih2, const float* __restrict__ bih2,
                     const float* __restrict__ Whh2, const float* __restrict__ bhh2,
                     float* __restrict__ out, int write_hidden)
{
    __shared__ __align__(16) float4 s_x [4][2][CH][8];    // x double buffer (role0)
    __shared__ __align__(16) u64    s_h0[4][2][CH][RS2];  // layer0 -> layer1 (+ self)
    __shared__ __align__(16) u64    s_h1[4][2][CH][RS2];  // layer1 -> layer2 (+ self)
    __shared__ __align__(16) u64    s_h2[4][2][CH][RS2];  // layer2 self

    const int tid  = threadIdx.x;
    const int wid  = tid >> 5;
    const int lane = tid & 31;
    const int k    = wid & 3;                   // chain index = SMSP
    const int role = wid >> 2;                  // 0..2 = layer
    const int bi   = k & 1;
    const int seg  = k >> 1;
    const int b    = blockIdx.x * 2 + bi;
    const int jj   = (lane < H_) ? lane : 0;    // clamped; dup lanes benign
    const bool act = (lane < H_);

    const int base_t = seg ? (HALF - BURN) : 0;
    const int NCH    = seg ? NC1 : NC0;

    u64 wA[16];      // layer0 input weight pairs
    u64 wP[9];       // layers 1/2 input-transform weight pairs
    u64 wR[9];       // recurrent weight pairs
    float bsum = 0.f, h = 0.f;

    if (role == 0) {
        const u64* wa = (const u64*)(Wih0 + jj * I_);
        const u64* wr = (const u64*)(Whh0 + jj * H_);
        #pragma unroll
        for (int m = 0; m < 16; ++m) wA[m] = __ldg(&wa[m]);
        #pragma unroll
        for (int m = 0; m < 9; ++m) wR[m] = __ldg(&wr[m]);
        bsum = __ldg(&bih0[jj]) + __ldg(&bhh0[jj]);
        h = seg ? 0.f : __ldg(&hidden[0 * B_ * H_ + b * H_ + jj]);
        ((float*)&s_h0[k][1][CH - 1][0])[jj] = h;        // seed c=-1 (own warp)
    } else if (role == 1) {
        const u64* wp = (const u64*)(Wih1 + jj * H_);
        const u64* wr = (const u64*)(Whh1 + jj * H_);
        #pragma unroll
        for (int m = 0; m < 9; ++m) { wP[m] = __ldg(&wp[m]); wR[m] = __ldg(&wr[m]); }
        bsum = __ldg(&bih1[jj]) + __ldg(&bhh1[jj]);
        h = seg ? 0.f : __ldg(&hidden[1 * B_ * H_ + b * H_ + jj]);
        ((float*)&s_h1[k][1][CH - 1][0])[jj] = h;
    } else {
        const u64* wp = (const u64*)(Wih2 + jj * H_);
        const u64* wr = (const u64*)(Whh2 + jj * H_);
        #pragma unroll
        for (int m = 0; m < 9; ++m) { wP[m] = __ldg(&wp[m]); wR[m] = __ldg(&wr[m]); }
        bsum = __ldg(&bih2[jj]) + __ldg(&bhh2[jj]);
        h = seg ? 0.f : __ldg(&hidden[2 * B_ * H_ + b * H_ + jj]);
        ((float*)&s_h2[k][1][CH - 1][0])[jj] = h;
    }
    const u64 binit = pack2(bsum, 0.f);

    u32 self_base = 0, pv_base = 0;
    const u32 x_base = (u32)__cvta_generic_to_shared(&s_x[k][0][0][0]);
    if (role == 0) {
        self_base = (u32)__cvta_generic_to_shared(&s_h0[k][0][0][0]);
    } else if (role == 1) {
        self_base = (u32)__cvta_generic_to_shared(&s_h1[k][0][0][0]);
        pv_base   = (u32)__cvta_generic_to_shared(&s_h0[k][0][0][0]);
    } else {
        self_base = (u32)__cvta_generic_to_shared(&s_h2[k][0][0][0]);
        pv_base   = (u32)__cvta_generic_to_shared(&s_h1[k][0][0][0]);
    }

    // role0: preload chunk 0 into x buffer 0 (same warp; volatile order).
    float4 xr[4];
    if (role == 0) {
        const float4* xg = (const float4*)(input + ((size_t)b * S_ + base_t) * I_);
        #pragma unroll
        for (int i = 0; i < 4; ++i) xr[i] = __ldg(&xg[lane + 32 * i]);
        #pragma unroll
        for (int i = 0; i < 4; ++i)
            sts_f128(x_base + (u32)(lane + 32 * i) * 16, xr[i]);
    }

    for (int ss = 0; ss < NC1 + 2; ++ss) {
        const int c = ss - role;
        if ((unsigned)c < (unsigned)NCH) {
            const int slot = c & 1;
            const int t0   = base_t + c * CH;
            if (role == 0) {
                // Prefetch next chunk's x early (latency hides behind steps).
                const bool pf = (c + 1) < NCH;
                if (pf) {
                    const float4* xg =
                        (const float4*)(input + ((size_t)b * S_ + t0 + CH) * I_);
                    #pragma unroll
                    for (int i = 0; i < 4; ++i) xr[i] = __ldg(&xg[lane + 32 * i]);
                }
                u32 xa  = x_base + slot * XCHB;
                u32 hp  = self_base + ((slot ^ 1) * CH + CH - 1) * ROWB;
                u32 cur = self_base + slot * CH * ROWB;
                #pragma unroll 4
                for (int t = 0; t < CH; ++t) {
                    u64 x0, x1, x2, x3, x4, x5, x6, x7;
                    u64 x8, x9, xA, xB, xC, xD, xE, xF;
                    lds_pair(xa,       x0, x1);  lds_pair(xa + 16,  x2, x3);
                    lds_pair(xa + 32,  x4, x5);  lds_pair(xa + 48,  x6, x7);
                    lds_pair(xa + 64,  x8, x9);  lds_pair(xa + 80,  xA, xB);
                    lds_pair(xa + 96,  xC, xD);  lds_pair(xa + 112, xE, xF);
                    u64 a0 = binit, a1 = 0ull, a2 = 0ull, a3 = 0ull;
                    fma2(a0, wA[0],  x0); fma2(a1, wA[1],  x1);
                    fma2(a2, wA[2],  x2); fma2(a3, wA[3],  x3);
                    fma2(a0, wA[4],  x4); fma2(a1, wA[5],  x5);
                    fma2(a2, wA[6],  x6); fma2(a3, wA[7],  x7);
                    fma2(a0, wA[8],  x8); fma2(a1, wA[9],  x9);
                    fma2(a2, wA[10], xA); fma2(a3, wA[11], xB);
                    fma2(a0, wA[12], xC); fma2(a1, wA[13], xD);
                    fma2(a2, wA[14], xE); fma2(a3, wA[15], xF);
                    a0 = add2(a0, a1); a2 = add2(a2, a3); a0 = add2(a0, a2);
                    const float pre = hsum2(a0);          // bit-identical to old xw
                    Acc A = { pack2(pre, 0.f), 0ull, 0ull };
                    rowdot(A, wR, hp);
                    h = finish(A);
                    sts_f32(cur + 4 * jj, h);
                    hp = cur; cur += ROWB; xa += 128;
                }
                if (pf) {
                    const u32 dst = x_base + ((c + 1) & 1) * XCHB;
                    #pragma unroll
                    for (int i = 0; i < 4; ++i)
                        sts_f128(dst + (u32)(lane + 32 * i) * 16, xr[i]);
                }
            } else {
                u32 hp  = self_base + ((slot ^ 1) * CH + CH - 1) * ROWB;
                u32 cur = self_base + slot * CH * ROWB;
                u32 pva = pv_base + slot * CH * ROWB;
                float* go = g_h2 + ((size_t)b * S_ + t0) * H_;
                const bool wr = (role == 2) && ((!seg) || (c >= BURNC));
                #pragma unroll 4
                for (int t = 0; t < CH; ++t) {
                    Acc A = { binit, 0ull, 0ull };
                    rowdot(A, wP, pva);      // producer row (barrier-separated)
                    rowdot(A, wR, hp);       // self row (same-warp ordered)
                    h = finish(A);
                    sts_f32(cur + 4 * jj, h);
                    if (wr) go[t * H_ + jj] = h;     // off-chain
                    hp = cur; cur += ROWB; pva += ROWB;
                }
            }
        }
        // Per-chain named barrier: 3 warps (96 threads) of chain k.
        asm volatile("bar.sync %0, %1;" :: "r"(k + 1), "r"(96) : "memory");
    }

    // Final hidden states come from segment-1 chains; role == layer.
    if (write_hidden && seg == 1 && act)
        out[(size_t)B_ * S_ + (size_t)role * B_ * H_ + b * H_ + lane] = h;
}

// ---------------------------------------------------------------------------
// Kernel B: MLP head (unchanged from best).
// ---------------------------------------------------------------------------
__global__ __launch_bounds__(256, 5)
void mlp_head_kernel(const float* __restrict__ W1, const float* __restrict__ b1,
                     const float* __restrict__ W2, const float* __restrict__ b2,
                     const float* __restrict__ W3, const float* __restrict__ b3,
                     const float* __restrict__ W4, const float* __restrict__ b4,
                     const float* __restrict__ W5, const float* __restrict__ b5,
                     const float* __restrict__ W6, const float* __restrict__ b6,
                     float* __restrict__ out)
{
    __shared__ u64 sROW[256 * 9];
    __shared__ u64 sW1[162], sW2[90], sW3[40], sW4[16], sW5[4];
    __shared__ float sb1[18], sb2[10], sb3[8], sb4[4], sb5[2], sW6f[2], sb6f[1];

    const int tid = threadIdx.x;
    if (tid < 162) sW1[tid] = __ldg((const u64*)W1 + tid);
    if (tid < 90)  sW2[tid] = __ldg((const u64*)W2 + tid);
    if (tid < 40)  sW3[tid] = __ldg((const u64*)W3 + tid);
    if (tid < 16)  sW4[tid] = __ldg((const u64*)W4 + tid);
    if (tid < 4)  { sW5[tid] = __ldg((const u64*)W5 + tid); sb4[tid] = b4[tid]; }
    if (tid < 18)  sb1[tid] = b1[tid];
    if (tid < 10)  sb2[tid] = b2[tid];
    if (tid < 8)   sb3[tid] = b3[tid];
    if (tid < 2)  { sb5[tid] = b5[tid]; sW6f[tid] = W6[tid]; }
    if (tid == 0)  sb6f[0] = b6[0];

    const size_t base = (size_t)blockIdx.x * 256;
    const u64* gh = (const u64*)g_h2 + base * 9;
    #pragma unroll
    for (int i = 0; i < 9; ++i) sROW[tid + i * 256] = __ldg(&gh[tid + i * 256]);
    __syncthreads();

    u64 a0[9];
    #pragma unroll
    for (int m = 0; m < 9; ++m) a0[m] = sROW[tid * 9 + m];

    float a1[18];
    #pragma unroll
    for (int j = 0; j < 18; ++j) {
        u64 acc = pack2(sb1[j], 0.f), accb = 0ull;
        #pragma unroll
        for (int m = 0; m < 9; ++m) fma2((m & 1) ? accb : acc, sW1[j * 9 + m], a0[m]);
        a1[j] = fmaxf(hsum2(add2(acc, accb)), 0.f);
    }
    u64 a1p[9];
    #pragma unroll
    for (int m = 0; m < 9; ++m) a1p[m] = pack2(a1[2 * m], a1[2 * m + 1]);

    float a2[10];
    #pragma unroll
    for (int j = 0; j < 10; ++j) {
        u64 acc = pack2(sb2[j], 0.f), accb = 0ull;
        #pragma unroll
        for (int m = 0; m < 9; ++m) fma2((m & 1) ? accb : acc, sW2[j * 9 + m], a1p[m]);
        a2[j] = fmaxf(hsum2(add2(acc, accb)), 0.f);
    }
    u64 a2p[5];
    #pragma unroll
    for (int m = 0; m < 5; ++m) a2p[m] = pack2(a2[2 * m], a2[2 * m + 1]);

    float a3[8];
    #pragma unroll
    for (int j = 0; j < 8; ++j) {
        u64 acc = pack2(sb3[j], 0.f), accb = 0ull;
        #pragma unroll
        for (int m = 0; m < 5; ++m) fma2((m & 1) ? accb : acc, sW3[j * 5 + m], a2p[m]);
        a3[j] = fmaxf(hsum2(add2(acc, accb)), 0.f);
    }
    u64 a3p[4];
    #pragma unroll
    for (int m = 0; m < 4; ++m) a3p[m] = pack2(a3[2 * m], a3[2 * m + 1]);

    float a4[4];
    #pragma unroll
    for (int j = 0; j < 4; ++j) {
        u64 acc = pack2(sb4[j], 0.f), accb = 0ull;
        #pragma unroll
        for (int m = 0; m < 4; ++m) fma2((m & 1) ? accb : acc, sW4[j * 4 + m], a3p[m]);
        a4[j] = fmaxf(hsum2(add2(acc, accb)), 0.f);
    }
    u64 a4p[2] = { pack2(a4[0], a4[1]), pack2(a4[2], a4[3]) };

    float a5[2];
    #pragma unroll
    for (int j = 0; j < 2; ++j) {
        u64 acc = pack2(sb5[j], 0.f);
        fma2(acc, sW5[j * 2 + 0], a4p[0]);
        fma2(acc, sW5[j * 2 + 1], a4p[1]);
        a5[j] = fmaxf(hsum2(acc), 0.f);
    }
    out[base + tid] = fmaf(a5[0], sW6f[0], fmaf(a5[1], sW6f[1], sb6f[0]));
}

// ---------------------------------------------------------------------------
// Launch
// ---------------------------------------------------------------------------
extern "C" void kernel_launch(void* const* d_in, const int* in_sizes, int n_in,
                              void* d_out, int out_size)
{
    const float* input  = (const float*)d_in[0];
    const float* hidden = (const float*)d_in[1];
    const float* Wih0 = (const float*)d_in[2];
    const float* bih0 = (const float*)d_in[3];
    const float* Whh0 = (const float*)d_in[4];
    const float* bhh0 = (const float*)d_in[5];
    const float* Wih1 = (const float*)d_in[6];
    const float* bih1 = (const float*)d_in[7];
    const float* Whh1 = (const float*)d_in[8];
    const float* bhh1 = (const float*)d_in[9];
    const float* Wih2 = (const float*)d_in[10];
    const float* bih2 = (const float*)d_in[11];
    const float* Whh2 = (const float*)d_in[12];
    const float* bhh2 = (const float*)d_in[13];
    const float* W1 = (const float*)d_in[14];
    const float* b1 = (const float*)d_in[15];
    const float* W2 = (const float*)d_in[16];
    const float* b2 = (const float*)d_in[17];
    const float* W3 = (const float*)d_in[18];
    const float* b3 = (const float*)d_in[19];
    const float* W4 = (const float*)d_in[20];
    const float* b4 = (const float*)d_in[21];
    const float* W5 = (const float*)d_in[22];
    const float* b5 = (const float*)d_in[23];
    const float* W6 = (const float*)d_in[24];
    const float* b6 = (const float*)d_in[25];

    float* out = (float*)d_out;
    const int write_hidden = (out_size >= B_ * S_ + 3 * B_ * H_) ? 1 : 0;

    rnn_scan_kernel<<<B_ / 2, 384>>>(input, hidden,
                                     Wih0, bih0, Whh0, bhh0,
                                     Wih1, bih1, Whh1, bhh1,
                                     Wih2, bih2, Whh2, bhh2,
                                     out, write_hidden);

    mlp_head_kernel<<<(B_ * S_) / 256, 256>>>(W1, b1, W2, b2, W3, b3,
                                              W4, b4, W5, b5, W6, b6, out);
}